// round 8
// baseline (speedup 1.0000x reference)
#include <cuda_runtime.h>
#include <cuda_bf16.h>
#include <math.h>

// Fixed shapes
#define B_ 32
#define C_ 6
#define T_ 64
#define K_ 8
#define N_ 128
#define NSEG 1016
#define NSEGP 1024
#define NCL 2048
#define NCLP2 1024             // candidate pairs
#define EPS_ 1e-6f
#define THRESH_ 0.5f
#define PAD_ 1e9f              // dummy-segment coordinate (kept modest so c1^2 stays finite)

#define THREADS 512
#define GL 64                  // lanes per point-group (2 warps)
#define NG 8                   // groups per block
#define M 4                    // points per group
#define PTS_BLK (NG * M)       // 32
#define HALVES (T_ / PTS_BLK)  // 2
// grid = B*C*HALVES = 384

typedef unsigned long long u64;

__device__ __forceinline__ u64 F2ADD(u64 a, u64 b) {
    u64 d; asm("add.rn.f32x2 %0,%1,%2;" : "=l"(d) : "l"(a), "l"(b)); return d;
}
__device__ __forceinline__ u64 F2MUL(u64 a, u64 b) {
    u64 d; asm("mul.rn.f32x2 %0,%1,%2;" : "=l"(d) : "l"(a), "l"(b)); return d;
}
__device__ __forceinline__ u64 F2FMA(u64 a, u64 b, u64 c) {
    u64 d; asm("fma.rn.f32x2 %0,%1,%2,%3;" : "=l"(d) : "l"(a), "l"(b), "l"(c)); return d;
}
__device__ __forceinline__ u64 F2PK(float lo, float hi) {
    u64 d; asm("mov.b64 %0,{%1,%2};" : "=l"(d) : "f"(lo), "f"(hi)); return d;
}
__device__ __forceinline__ void F2UP(u64 a, float& lo, float& hi) {
    asm("mov.b64 {%0,%1},%2;" : "=f"(lo), "=f"(hi) : "l"(a));
}

__global__ void offroad_init_kernel(float* out) {
    int i = threadIdx.x;
    if (i < B_ * C_) out[i] = 0.0f;
}

__global__ __launch_bounds__(THREADS, 2)
void offroad_kernel(const float* __restrict__ points,
                    const float* __restrict__ road_boundary,
                    const float* __restrict__ centerlines,
                    float* __restrict__ out) {
    __shared__ float4 sA[NSEGP];     // (-ax,-ax,-ay,-ay)
    __shared__ float4 sD[NSEGP];     // (-dx,-dx,-dy,-dy)
    __shared__ float4 sG[NSEGP];     // (gx,gx,gy,gy), g = d*inv
    __shared__ float2 sX[NSEGP];     // (dx,dx)
    __shared__ float4 sCl[NCLP2];    // (-qx0,-qx1,-qy0,-qy1) per cand pair
    __shared__ float2 sClh[NCLP2];   // (h0,h1) = 0.5*|q|^2 per pair
    __shared__ float2 sRedA[NG][2][M];
    __shared__ float  sRedM[NG][2][M];
    __shared__ u64    sRedH[NG][2][2];

    const int bid = blockIdx.x;
    const int half = bid & 1;
    const int c = (bid >> 1) % C_;
    const int b = bid / (2 * C_);
    const int tid = threadIdx.x;

    // ---- fill segments ----
    {
        const float2* rb = (const float2*)road_boundary + (size_t)b * K_ * N_;
        #pragma unroll
        for (int s0 = 0; s0 < NSEGP; s0 += THREADS) {
            int s = s0 + tid;
            float nax, nay, ndx, ndy, gx, gy, dx;
            if (s < NSEG) {
                int k = s / (N_ - 1);
                int j = s - k * (N_ - 1);
                float2 a = rb[k * N_ + j];
                float2 e = rb[k * N_ + j + 1];
                nax = -a.x; nay = -a.y;
                dx = e.x - a.x;
                float dy = e.y - a.y;
                ndx = -dx; ndy = -dy;
                float inv = 1.0f / (fmaf(dx, dx, dy * dy) + EPS_);
                gx = dx * inv; gy = dy * inv;
            } else {
                nax = -PAD_; nay = -PAD_;
                ndx = 0.0f; ndy = 0.0f; gx = 0.0f; gy = 0.0f; dx = 0.0f;
            }
            sA[s] = make_float4(nax, nax, nay, nay);
            sD[s] = make_float4(ndx, ndx, ndy, ndy);
            sG[s] = make_float4(gx, gx, gy, gy);
            sX[s] = make_float2(dx, dx);
        }
    }
    // ---- fill centerlines (negated pair-SoA + half-norms) ----
    {
        const float4* cl4 = (const float4*)(centerlines + (size_t)b * NCL * 2);
        #pragma unroll
        for (int p0 = 0; p0 < NCLP2; p0 += THREADS) {
            int pi = p0 + tid;
            float4 v = cl4[pi];     // (q0x,q0y,q1x,q1y)
            sCl[pi] = make_float4(-v.x, -v.z, -v.y, -v.w);
            sClh[pi] = make_float2(0.5f * fmaf(v.x, v.x, v.y * v.y),
                                   0.5f * fmaf(v.z, v.z, v.w * v.w));
        }
    }
    __syncthreads();

    const int grp = tid >> 6;        // 0..7
    const int wig = (tid >> 5) & 1;  // warp in group
    const int lG  = tid & 63;        // lane in group

    float px[M], py[M];
    {
        const float2* pp = (const float2*)points +
            ((size_t)(b * C_ + c)) * T_ + half * PTS_BLK + grp * M;
        #pragma unroll
        for (int j = 0; j < M; j++) { float2 p = pp[j]; px[j] = p.x; py[j] = p.y; }
    }

    // ---- Phase A: argmin over candidates (score = 0.5|q|^2 - p.q, packed pairs) ----
    u64 pxd[M], pyd[M];
    #pragma unroll
    for (int j = 0; j < M; j++) { pxd[j] = F2PK(px[j], px[j]); pyd[j] = F2PK(py[j], py[j]); }

    float sc[M]; int bi[M];
    #pragma unroll
    for (int j = 0; j < M; j++) { sc[j] = 3.4e38f; bi[j] = 0; }

    const u64* clh64 = (const u64*)sClh;
    #pragma unroll 4
    for (int it = 0; it < NCLP2 / GL; it++) {       // 16 iters
        int pi = lG + it * GL;
        float4 nq = sCl[pi];
        u64 h2  = clh64[pi];
        u64 nqx = F2PK(nq.x, nq.y);
        u64 nqy = F2PK(nq.z, nq.w);
        int c0 = 2 * pi;
        #pragma unroll
        for (int j = 0; j < M; j++) {
            u64 s2 = F2FMA(pxd[j], nqx, F2FMA(pyd[j], nqy, h2));
            float s0, s1; F2UP(s2, s0, s1);
            float pmin = fminf(s0, s1);
            int   pidx = c0 + ((s1 < s0) ? 1 : 0);
            if (pmin < sc[j]) { sc[j] = pmin; bi[j] = pidx; }
        }
    }
    #pragma unroll
    for (int off = 16; off; off >>= 1) {
        #pragma unroll
        for (int j = 0; j < M; j++) {
            float os = __shfl_xor_sync(0xffffffffu, sc[j], off);
            int   oi = __shfl_xor_sync(0xffffffffu, bi[j], off);
            if (os < sc[j] || (os == sc[j] && oi < bi[j])) { sc[j] = os; bi[j] = oi; }
        }
    }
    if ((tid & 31) == 0) {
        #pragma unroll
        for (int j = 0; j < M; j++)
            sRedA[grp][wig][j] = make_float2(sc[j], __int_as_float(bi[j]));
    }
    __syncthreads();
    #pragma unroll
    for (int j = 0; j < M; j++) {
        float2 e0 = sRedA[grp][0][j];
        float2 e1 = sRedA[grp][1][j];
        int i0 = __float_as_int(e0.y), i1 = __float_as_int(e1.y);
        bi[j] = (e1.x < e0.x || (e1.x == e0.x && i1 < i0)) ? i1 : i0;
    }

    // per-pair packed constants
    float dax[M], day[M];
    const float* clf = (const float*)sCl;
    #pragma unroll
    for (int j = 0; j < M; j++) {
        int p_ = bi[j] >> 1, h_ = bi[j] & 1;
        float nqx = clf[p_ * 4 + h_];
        float nqy = clf[p_ * 4 + 2 + h_];
        dax[j] = -nqx - px[j];     // qx - px
        day[j] = -nqy - py[j];
    }
    u64 px2[2]   = { F2PK(px[0], px[1]),   F2PK(px[2], px[3]) };
    u64 py2[2]   = { F2PK(py[0], py[1]),   F2PK(py[2], py[3]) };
    u64 dax2[2]  = { F2PK(dax[0], dax[1]), F2PK(dax[2], dax[3]) };
    u64 nday2[2] = { F2PK(-day[0], -day[1]), F2PK(-day[2], -day[3]) };
    const u64 neps2 = F2PK(-EPS_, -EPS_);

    // ---- Phase B: fused distance + intersection over segments ----
    float mind2[M];
    u64 hbits[2];
    #pragma unroll
    for (int j = 0; j < M; j++) mind2[j] = 3.4e38f;
    hbits[0] = 0ull; hbits[1] = 0ull;

    const u64* sx64 = (const u64*)sX;
    #pragma unroll 4
    for (int it = 0; it < NSEGP / GL; it++) {       // 16 iters
        int s = lG + it * GL;
        float4 A = sA[s];
        float4 D = sD[s];
        float4 G = sG[s];
        u64 dx2  = sx64[s];
        u64 nax2 = F2PK(A.x, A.y), nay2 = F2PK(A.z, A.w);
        u64 ndx2 = F2PK(D.x, D.y), ndy2 = F2PK(D.z, D.w);
        u64 gx2  = F2PK(G.x, G.y), gy2  = F2PK(G.z, G.w);
        #pragma unroll
        for (int q = 0; q < 2; q++) {
            int j0 = 2 * q, j1 = 2 * q + 1;
            u64 v1x = F2ADD(px2[q], nax2);          // p - a
            u64 v1y = F2ADD(py2[q], nay2);
            u64 pr  = F2FMA(v1y, gy2, F2MUL(v1x, gx2));   // dot * inv
            float p0, p1; F2UP(pr, p0, p1);
            p0 = __saturatef(p0); p1 = __saturatef(p1);
            pr = F2PK(p0, p1);
            u64 ex = F2FMA(ndx2, pr, v1x);          // v1x - dx*pr
            u64 ey = F2FMA(ndy2, pr, v1y);
            u64 d2 = F2FMA(ey, ey, F2MUL(ex, ex));
            float d20, d21; F2UP(d2, d20, d21);
            mind2[j0] = fminf(mind2[j0], d20);
            mind2[j1] = fminf(mind2[j1], d21);
            // nw = -(cross(da,db)+eps); c1 = cross(da,v1); c2 = cross(db,v1)
            u64 nw = F2FMA(nday2[q], ndx2, F2FMA(dax2[q], ndy2, neps2));
            u64 c1 = F2FMA(dax2[q], v1y, F2MUL(nday2[q], v1x));
            u64 c2 = F2FMA(dx2,     v1y, F2MUL(ndy2,     v1x));
            u64 s1 = F2MUL(c1, F2ADD(c1, nw));      // c1*(c1-w): hit-half iff sign set
            u64 s2 = F2MUL(c2, F2ADD(c2, nw));
            hbits[q] |= (s1 & s2);                  // LOP3: sign bits AND, accumulate OR
        }
    }
    #pragma unroll
    for (int off = 16; off; off >>= 1) {
        #pragma unroll
        for (int j = 0; j < M; j++)
            mind2[j] = fminf(mind2[j], __shfl_xor_sync(0xffffffffu, mind2[j], off));
        #pragma unroll
        for (int q = 0; q < 2; q++)
            hbits[q] |= __shfl_xor_sync(0xffffffffu, hbits[q], off);
    }
    if ((tid & 31) == 0) {
        #pragma unroll
        for (int j = 0; j < M; j++) sRedM[grp][wig][j] = mind2[j];
        sRedH[grp][wig][0] = hbits[0];
        sRedH[grp][wig][1] = hbits[1];
    }
    __syncthreads();

    // warp 0: one thread per point (32 points), reduce and accumulate
    if (tid < 32) {
        int g_ = tid >> 2, j_ = tid & 3;
        float md2 = fminf(sRedM[g_][0][j_], sRedM[g_][1][j_]);
        u64 hb = sRedH[g_][0][j_ >> 1] | sRedH[g_][1][j_ >> 1];
        unsigned hw = (j_ & 1) ? (unsigned)(hb >> 32) : (unsigned)hb;
        float md = sqrtf(md2);
        md = (hw & 0x80000000u) ? md : -md;   // sign set => intersect => outside (+)
        float term = fmaxf(md + THRESH_, 0.0f);
        #pragma unroll
        for (int off = 16; off; off >>= 1)
            term += __shfl_xor_sync(0xffffffffu, term, off);
        if (tid == 0) atomicAdd(&out[b * C_ + c], term);
    }
}

extern "C" void kernel_launch(void* const* d_in, const int* in_sizes, int n_in,
                              void* d_out, int out_size) {
    const float* points      = (const float*)d_in[0];
    const float* road_bound  = (const float*)d_in[1];
    const float* centerlines = (const float*)d_in[2];
    float* out = (float*)d_out;
    (void)in_sizes; (void)n_in; (void)out_size;

    offroad_init_kernel<<<1, 256>>>(out);
    offroad_kernel<<<B_ * C_ * HALVES, THREADS>>>(points, road_bound, centerlines, out);
}

// round 9
// speedup vs baseline: 1.0012x; 1.0012x over previous
#include <cuda_runtime.h>
#include <cuda_bf16.h>
#include <math.h>

// Fixed shapes
#define B_ 32
#define C_ 6
#define T_ 64
#define K_ 8
#define N_ 128
#define NSEG 1016
#define NSEGP 1024
#define NCL 2048
#define NCLP2 1024             // candidate pairs
#define EPS_ 1e-6f
#define THRESH_ 0.5f
#define PAD_ 1e9f              // dummy-segment anchor

#define THREADS 512
#define GL 64                  // lanes per point-group (2 warps)
#define NG 8                   // groups per block
#define M 4                    // points per group
#define PTS_BLK (NG * M)       // 32
#define HALVES (T_ / PTS_BLK)  // 2
// grid = B*C*HALVES = 384

typedef unsigned long long u64;

__device__ __forceinline__ u64 F2ADD(u64 a, u64 b) {
    u64 d; asm("add.rn.f32x2 %0,%1,%2;" : "=l"(d) : "l"(a), "l"(b)); return d;
}
__device__ __forceinline__ u64 F2SUB(u64 a, u64 b) {
    u64 d; asm("sub.rn.f32x2 %0,%1,%2;" : "=l"(d) : "l"(a), "l"(b)); return d;
}
__device__ __forceinline__ u64 F2MUL(u64 a, u64 b) {
    u64 d; asm("mul.rn.f32x2 %0,%1,%2;" : "=l"(d) : "l"(a), "l"(b)); return d;
}
__device__ __forceinline__ u64 F2FMA(u64 a, u64 b, u64 c) {
    u64 d; asm("fma.rn.f32x2 %0,%1,%2,%3;" : "=l"(d) : "l"(a), "l"(b), "l"(c)); return d;
}
__device__ __forceinline__ u64 F2PK(float lo, float hi) {
    u64 d; asm("mov.b64 %0,{%1,%2};" : "=l"(d) : "f"(lo), "f"(hi)); return d;
}
__device__ __forceinline__ void F2UP(u64 a, float& lo, float& hi) {
    asm("mov.b64 {%0,%1},%2;" : "=f"(lo), "=f"(hi) : "l"(a));
}
__device__ __forceinline__ float frcp(float x) {
    float r; asm("rcp.approx.f32 %0,%1;" : "=f"(r) : "f"(x)); return r;
}

__global__ void offroad_init_kernel(float* out) {
    int i = threadIdx.x;
    if (i < B_ * C_) out[i] = 0.0f;
}

__global__ __launch_bounds__(THREADS, 2)
void offroad_kernel(const float* __restrict__ points,
                    const float* __restrict__ road_boundary,
                    const float* __restrict__ centerlines,
                    float* __restrict__ out) {
    __shared__ float4 sA[NSEGP];     // (-ax,-ax,-ay,-ay)
    __shared__ float4 sD[NSEGP];     // (-dx,-dx,-dy,-dy)
    __shared__ float4 sCl[NCLP2];    // (-qx0,-qx1,-qy0,-qy1) per cand pair
    __shared__ float2 sClh[NCLP2];   // (h0,h1) = 0.5*|q|^2 per pair
    __shared__ float2 sRedA[NG][2][M];
    __shared__ float  sRedM[NG][2][M];
    __shared__ u64    sRedH[NG][2][2];

    const int bid = blockIdx.x;
    const int half = bid & 1;
    const int c = (bid >> 1) % C_;
    const int b = bid / (2 * C_);
    const int tid = threadIdx.x;

    // ---- fill segments (padded with far-away inert unit segments) ----
    {
        const float2* rb = (const float2*)road_boundary + (size_t)b * K_ * N_;
        #pragma unroll
        for (int s0 = 0; s0 < NSEGP; s0 += THREADS) {
            int s = s0 + tid;
            float nax, nay, ndx, ndy;
            if (s < NSEG) {
                int k = s / (N_ - 1);
                int j = s - k * (N_ - 1);
                float2 a = rb[k * N_ + j];
                float2 e = rb[k * N_ + j + 1];
                nax = -a.x; nay = -a.y;
                ndx = a.x - e.x; ndy = a.y - e.y;
            } else {
                nax = -PAD_; nay = -PAD_;   // a = (PAD, PAD)
                ndx = -1.0f; ndy = 0.0f;    // d = (1, 0): real but far segment
            }
            sA[s] = make_float4(nax, nax, nay, nay);
            sD[s] = make_float4(ndx, ndx, ndy, ndy);
        }
    }
    // ---- fill centerlines (negated pair-SoA + half-norms) ----
    {
        const float4* cl4 = (const float4*)(centerlines + (size_t)b * NCL * 2);
        #pragma unroll
        for (int p0 = 0; p0 < NCLP2; p0 += THREADS) {
            int pi = p0 + tid;
            float4 v = cl4[pi];     // (q0x,q0y,q1x,q1y)
            sCl[pi] = make_float4(-v.x, -v.z, -v.y, -v.w);
            sClh[pi] = make_float2(0.5f * fmaf(v.x, v.x, v.y * v.y),
                                   0.5f * fmaf(v.z, v.z, v.w * v.w));
        }
    }
    __syncthreads();

    const int grp = tid >> 6;        // 0..7
    const int wig = (tid >> 5) & 1;  // warp in group
    const int lG  = tid & 63;        // lane in group

    float px[M], py[M];
    {
        const float2* pp = (const float2*)points +
            ((size_t)(b * C_ + c)) * T_ + half * PTS_BLK + grp * M;
        #pragma unroll
        for (int j = 0; j < M; j++) { float2 p = pp[j]; px[j] = p.x; py[j] = p.y; }
    }

    // ---- Phase A: argmin over candidates (score = 0.5|q|^2 - p.q, packed pairs) ----
    u64 pxd[M], pyd[M];
    #pragma unroll
    for (int j = 0; j < M; j++) { pxd[j] = F2PK(px[j], px[j]); pyd[j] = F2PK(py[j], py[j]); }

    float sc[M]; int bi[M];
    #pragma unroll
    for (int j = 0; j < M; j++) { sc[j] = 3.4e38f; bi[j] = 0; }

    const u64* clh64 = (const u64*)sClh;
    #pragma unroll
    for (int it = 0; it < NCLP2 / GL; it++) {       // 16 iters, fully unrolled
        int pi = lG + it * GL;
        float4 nq = sCl[pi];
        u64 h2  = clh64[pi];
        u64 nqx = F2PK(nq.x, nq.y);
        u64 nqy = F2PK(nq.z, nq.w);
        int c0 = 2 * pi;
        #pragma unroll
        for (int j = 0; j < M; j++) {
            u64 s2 = F2FMA(pxd[j], nqx, F2FMA(pyd[j], nqy, h2));
            float s0, s1; F2UP(s2, s0, s1);
            float pmin = fminf(s0, s1);
            int   pidx = c0 + ((s1 < s0) ? 1 : 0);
            if (pmin < sc[j]) { sc[j] = pmin; bi[j] = pidx; }
        }
    }
    #pragma unroll
    for (int off = 16; off; off >>= 1) {
        #pragma unroll
        for (int j = 0; j < M; j++) {
            float os = __shfl_xor_sync(0xffffffffu, sc[j], off);
            int   oi = __shfl_xor_sync(0xffffffffu, bi[j], off);
            if (os < sc[j] || (os == sc[j] && oi < bi[j])) { sc[j] = os; bi[j] = oi; }
        }
    }
    if ((tid & 31) == 0) {
        #pragma unroll
        for (int j = 0; j < M; j++)
            sRedA[grp][wig][j] = make_float2(sc[j], __int_as_float(bi[j]));
    }
    __syncthreads();
    #pragma unroll
    for (int j = 0; j < M; j++) {
        float2 e0 = sRedA[grp][0][j];
        float2 e1 = sRedA[grp][1][j];
        int i0 = __float_as_int(e0.y), i1 = __float_as_int(e1.y);
        bi[j] = (e1.x < e0.x || (e1.x == e0.x && i1 < i0)) ? i1 : i0;
    }

    // per-pair packed constants
    float dax[M], day[M];
    const float* clf = (const float*)sCl;
    #pragma unroll
    for (int j = 0; j < M; j++) {
        int p_ = bi[j] >> 1, h_ = bi[j] & 1;
        float nqx = clf[p_ * 4 + h_];
        float nqy = clf[p_ * 4 + 2 + h_];
        dax[j] = -nqx - px[j];     // qx - px
        day[j] = -nqy - py[j];
    }
    u64 px2[2]   = { F2PK(px[0], px[1]),   F2PK(px[2], px[3]) };
    u64 py2[2]   = { F2PK(py[0], py[1]),   F2PK(py[2], py[3]) };
    u64 dax2[2]  = { F2PK(dax[0], dax[1]), F2PK(dax[2], dax[3]) };
    u64 nday2[2] = { F2PK(-day[0], -day[1]), F2PK(-day[2], -day[3]) };
    const u64 neps2 = F2PK(-EPS_, -EPS_);

    // ---- Phase B: fused distance + intersection over segments ----
    float mind2[M];
    u64 hbits[2];
    #pragma unroll
    for (int j = 0; j < M; j++) mind2[j] = 3.4e38f;
    hbits[0] = 0ull; hbits[1] = 0ull;

    #pragma unroll
    for (int it = 0; it < NSEGP / GL; it++) {       // 16 iters, fully unrolled
        int s = lG + it * GL;
        float4 A = sA[s];
        float4 D = sD[s];
        u64 nax2 = F2PK(A.x, A.y), nay2 = F2PK(A.z, A.w);
        u64 ndx2 = F2PK(D.x, D.y), ndy2 = F2PK(D.z, D.w);
        float len2 = fmaf(D.x, D.x, fmaf(D.z, D.z, EPS_));
        float negr = -frcp(len2);
        #pragma unroll
        for (int q = 0; q < 2; q++) {
            int j0 = 2 * q, j1 = 2 * q + 1;
            u64 v1x = F2ADD(px2[q], nax2);          // p - a
            u64 v1y = F2ADD(py2[q], nay2);
            u64 ndt = F2FMA(v1y, ndy2, F2MUL(v1x, ndx2));   // -(v1.d)
            float n0, n1; F2UP(ndt, n0, n1);
            float p0 = __saturatef(n0 * negr);       // FMUL.SAT
            float p1 = __saturatef(n1 * negr);
            u64 pr = F2PK(p0, p1);
            u64 ex = F2FMA(ndx2, pr, v1x);          // v1x - dx*pr
            u64 ey = F2FMA(ndy2, pr, v1y);
            u64 d2 = F2FMA(ey, ey, F2MUL(ex, ex));
            float d20, d21; F2UP(d2, d20, d21);
            mind2[j0] = fminf(mind2[j0], d20);
            mind2[j1] = fminf(mind2[j1], d21);
            // nw = -(cross(da,db)+eps); c1 = cross(da,v1); c2 = cross(db,v1)
            u64 nw = F2FMA(nday2[q], ndx2, F2FMA(dax2[q], ndy2, neps2));
            u64 c1 = F2FMA(dax2[q], v1y, F2MUL(nday2[q], v1x));
            u64 c2 = F2SUB(F2MUL(ndy2, v1x), F2MUL(ndx2, v1y));
            u64 s1 = F2MUL(c1, F2ADD(c1, nw));      // c1*(c1-w): half-hit iff sign set
            u64 s2 = F2MUL(c2, F2ADD(c2, nw));
            hbits[q] |= (s1 & s2);                  // LOP3 sign-AND, OR-accumulate
        }
    }
    #pragma unroll
    for (int off = 16; off; off >>= 1) {
        #pragma unroll
        for (int j = 0; j < M; j++)
            mind2[j] = fminf(mind2[j], __shfl_xor_sync(0xffffffffu, mind2[j], off));
        #pragma unroll
        for (int q = 0; q < 2; q++)
            hbits[q] |= __shfl_xor_sync(0xffffffffu, hbits[q], off);
    }
    if ((tid & 31) == 0) {
        #pragma unroll
        for (int j = 0; j < M; j++) sRedM[grp][wig][j] = mind2[j];
        sRedH[grp][wig][0] = hbits[0];
        sRedH[grp][wig][1] = hbits[1];
    }
    __syncthreads();

    // warp 0: one thread per point (32 points), reduce and accumulate
    if (tid < 32) {
        int g_ = tid >> 2, j_ = tid & 3;
        float md2 = fminf(sRedM[g_][0][j_], sRedM[g_][1][j_]);
        u64 hb = sRedH[g_][0][j_ >> 1] | sRedH[g_][1][j_ >> 1];
        unsigned hw = (j_ & 1) ? (unsigned)(hb >> 32) : (unsigned)hb;
        float md = sqrtf(md2);
        md = (hw & 0x80000000u) ? md : -md;   // sign set => intersect => outside (+)
        float term = fmaxf(md + THRESH_, 0.0f);
        #pragma unroll
        for (int off = 16; off; off >>= 1)
            term += __shfl_xor_sync(0xffffffffu, term, off);
        if (tid == 0) atomicAdd(&out[b * C_ + c], term);
    }
}

extern "C" void kernel_launch(void* const* d_in, const int* in_sizes, int n_in,
                              void* d_out, int out_size) {
    const float* points      = (const float*)d_in[0];
    const float* road_bound  = (const float*)d_in[1];
    const float* centerlines = (const float*)d_in[2];
    float* out = (float*)d_out;
    (void)in_sizes; (void)n_in; (void)out_size;

    offroad_init_kernel<<<1, 256>>>(out);
    offroad_kernel<<<B_ * C_ * HALVES, THREADS>>>(points, road_bound, centerlines, out);
}

// round 10
// speedup vs baseline: 1.1889x; 1.1875x over previous
#include <cuda_runtime.h>
#include <cuda_bf16.h>
#include <math.h>

// Fixed shapes
#define B_ 32
#define C_ 6
#define T_ 64
#define K_ 8
#define N_ 128
#define NSEG 1016
#define NSEGP 1024
#define NCL 2048
#define NCLP2 1024             // candidate pairs
#define EPS_ 1e-6f
#define THRESH_ 0.5f
#define PAD_ 1e9f

#define THREADS 256
#define WARPS 8                // each warp = independent point group
#define M 4                    // points per warp
#define PTS_BLK (WARPS * M)    // 32
#define HALVES (T_ / PTS_BLK)  // 2
// grid = B*C*HALVES = 384

typedef unsigned long long u64;

__device__ float    g_scratch[B_ * C_ * 2];   // zero-init (.bss)
__device__ unsigned g_tick[B_ * C_];          // zero-init, reset after use

__device__ __forceinline__ u64 F2ADD(u64 a, u64 b) {
    u64 d; asm("add.rn.f32x2 %0,%1,%2;" : "=l"(d) : "l"(a), "l"(b)); return d;
}
__device__ __forceinline__ u64 F2SUB(u64 a, u64 b) {
    u64 d; asm("sub.rn.f32x2 %0,%1,%2;" : "=l"(d) : "l"(a), "l"(b)); return d;
}
__device__ __forceinline__ u64 F2MUL(u64 a, u64 b) {
    u64 d; asm("mul.rn.f32x2 %0,%1,%2;" : "=l"(d) : "l"(a), "l"(b)); return d;
}
__device__ __forceinline__ u64 F2FMA(u64 a, u64 b, u64 c) {
    u64 d; asm("fma.rn.f32x2 %0,%1,%2,%3;" : "=l"(d) : "l"(a), "l"(b), "l"(c)); return d;
}
__device__ __forceinline__ u64 F2PK(float lo, float hi) {
    u64 d; asm("mov.b64 %0,{%1,%2};" : "=l"(d) : "f"(lo), "f"(hi)); return d;
}
__device__ __forceinline__ void F2UP(u64 a, float& lo, float& hi) {
    asm("mov.b64 {%0,%1},%2;" : "=f"(lo), "=f"(hi) : "l"(a));
}
__device__ __forceinline__ float frcp(float x) {
    float r; asm("rcp.approx.f32 %0,%1;" : "=f"(r) : "f"(x)); return r;
}

__global__ __launch_bounds__(THREADS, 3)
void offroad_kernel(const float* __restrict__ points,
                    const float* __restrict__ road_boundary,
                    const float* __restrict__ centerlines,
                    float* __restrict__ out) {
    __shared__ float4 sA[NSEGP];     // (-ax,-ax,-ay,-ay)
    __shared__ float4 sD[NSEGP];     // (-dx,-dx,-dy,-dy)
    __shared__ float4 sCl[NCLP2];    // (-qx0,-qx1,-qy0,-qy1) per cand pair
    __shared__ float2 sClh[NCLP2];   // (h0,h1) = 0.5*|q|^2 per pair
    __shared__ float  sVal[WARPS];

    const int bid = blockIdx.x;
    const int half = bid & 1;
    const int c = (bid >> 1) % C_;
    const int b = bid / (2 * C_);
    const int idx = b * C_ + c;
    const int tid = threadIdx.x;

    // ---- fill segments (padded with far-away inert unit segments) ----
    {
        const float2* rb = (const float2*)road_boundary + (size_t)b * K_ * N_;
        #pragma unroll
        for (int s0 = 0; s0 < NSEGP; s0 += THREADS) {
            int s = s0 + tid;
            float nax, nay, ndx, ndy;
            if (s < NSEG) {
                int k = s / (N_ - 1);
                int j = s - k * (N_ - 1);
                float2 a = rb[k * N_ + j];
                float2 e = rb[k * N_ + j + 1];
                nax = -a.x; nay = -a.y;
                ndx = a.x - e.x; ndy = a.y - e.y;
            } else {
                nax = -PAD_; nay = -PAD_;   // a = (PAD, PAD), d = (1,0): inert
                ndx = -1.0f; ndy = 0.0f;
            }
            sA[s] = make_float4(nax, nax, nay, nay);
            sD[s] = make_float4(ndx, ndx, ndy, ndy);
        }
    }
    // ---- fill centerlines (negated pair-SoA + half-norms) ----
    {
        const float4* cl4 = (const float4*)(centerlines + (size_t)b * NCL * 2);
        #pragma unroll
        for (int p0 = 0; p0 < NCLP2; p0 += THREADS) {
            int pi = p0 + tid;
            float4 v = cl4[pi];     // (q0x,q0y,q1x,q1y)
            sCl[pi] = make_float4(-v.x, -v.z, -v.y, -v.w);
            sClh[pi] = make_float2(0.5f * fmaf(v.x, v.x, v.y * v.y),
                                   0.5f * fmaf(v.z, v.z, v.w * v.w));
        }
    }
    __syncthreads();

    const int w = tid >> 5;     // warp = point group (0..7)
    const int l = tid & 31;

    float px[M], py[M];
    {
        const float2* pp = (const float2*)points +
            ((size_t)idx) * T_ + half * PTS_BLK + w * M;
        #pragma unroll
        for (int j = 0; j < M; j++) { float2 p = pp[j]; px[j] = p.x; py[j] = p.y; }
    }

    // ---- Phase A: argmin over candidate pairs (score = 0.5|q|^2 - p.q) ----
    u64 pxd[M], pyd[M];
    #pragma unroll
    for (int j = 0; j < M; j++) { pxd[j] = F2PK(px[j], px[j]); pyd[j] = F2PK(py[j], py[j]); }

    float sc[M]; int bp[M];     // best pair score / pair index
    #pragma unroll
    for (int j = 0; j < M; j++) { sc[j] = 3.4e38f; bp[j] = 0; }

    const u64* clh64 = (const u64*)sClh;
    #pragma unroll 8
    for (int it = 0; it < NCLP2 / 32; it++) {       // 32 iters
        int pi = l + it * 32;
        float4 nq = sCl[pi];
        u64 h2  = clh64[pi];
        u64 nqx = F2PK(nq.x, nq.y);
        u64 nqy = F2PK(nq.z, nq.w);
        #pragma unroll
        for (int j = 0; j < M; j++) {
            u64 s2 = F2FMA(pxd[j], nqx, F2FMA(pyd[j], nqy, h2));
            float s0, s1; F2UP(s2, s0, s1);
            float pmin = fminf(s0, s1);
            if (pmin < sc[j]) { sc[j] = pmin; bp[j] = pi; }
        }
    }
    #pragma unroll
    for (int off = 16; off; off >>= 1) {
        #pragma unroll
        for (int j = 0; j < M; j++) {
            float os = __shfl_xor_sync(0xffffffffu, sc[j], off);
            int   oi = __shfl_xor_sync(0xffffffffu, bp[j], off);
            if (os < sc[j] || (os == sc[j] && oi < bp[j])) { sc[j] = os; bp[j] = oi; }
        }
    }
    // resolve which half of the winning pair (recompute one packed score)
    float dax[M], day[M];
    #pragma unroll
    for (int j = 0; j < M; j++) {
        float4 nq = sCl[bp[j]];         // broadcast
        u64 h2 = clh64[bp[j]];
        u64 s2 = F2FMA(pxd[j], F2PK(nq.x, nq.y),
                 F2FMA(pyd[j], F2PK(nq.z, nq.w), h2));
        float s0, s1; F2UP(s2, s0, s1);
        bool h1 = (s1 < s0);            // tie -> half 0 (lower index)
        float nqx = h1 ? nq.y : nq.x;
        float nqy = h1 ? nq.w : nq.z;
        dax[j] = -nqx - px[j];          // qx - px
        day[j] = -nqy - py[j];
    }
    u64 px2[2]   = { F2PK(px[0], px[1]),   F2PK(px[2], px[3]) };
    u64 py2[2]   = { F2PK(py[0], py[1]),   F2PK(py[2], py[3]) };
    u64 dax2[2]  = { F2PK(dax[0], dax[1]), F2PK(dax[2], dax[3]) };
    u64 nday2[2] = { F2PK(-day[0], -day[1]), F2PK(-day[2], -day[3]) };
    const u64 neps2 = F2PK(-EPS_, -EPS_);

    // ---- Phase B: fused distance + intersection over segments ----
    float mind2[M];
    u64 hbits[2];
    #pragma unroll
    for (int j = 0; j < M; j++) mind2[j] = 3.4e38f;
    hbits[0] = 0ull; hbits[1] = 0ull;

    #pragma unroll 8
    for (int it = 0; it < NSEGP / 32; it++) {       // 32 iters
        int s = l + it * 32;
        float4 A = sA[s];
        float4 D = sD[s];
        u64 nax2 = F2PK(A.x, A.y), nay2 = F2PK(A.z, A.w);
        u64 ndx2 = F2PK(D.x, D.y), ndy2 = F2PK(D.z, D.w);
        float len2 = fmaf(D.x, D.x, fmaf(D.z, D.z, EPS_));
        float negr = -frcp(len2);
        #pragma unroll
        for (int q = 0; q < 2; q++) {
            int j0 = 2 * q, j1 = 2 * q + 1;
            u64 v1x = F2ADD(px2[q], nax2);          // p - a
            u64 v1y = F2ADD(py2[q], nay2);
            u64 ndt = F2FMA(v1y, ndy2, F2MUL(v1x, ndx2));   // -(v1.d)
            float n0, n1; F2UP(ndt, n0, n1);
            float p0 = __saturatef(n0 * negr);       // FMUL.SAT
            float p1 = __saturatef(n1 * negr);
            u64 pr = F2PK(p0, p1);
            u64 ex = F2FMA(ndx2, pr, v1x);          // v1x - dx*pr
            u64 ey = F2FMA(ndy2, pr, v1y);
            u64 d2 = F2FMA(ey, ey, F2MUL(ex, ex));
            float d20, d21; F2UP(d2, d20, d21);
            mind2[j0] = fminf(mind2[j0], d20);
            mind2[j1] = fminf(mind2[j1], d21);
            // nw = -(cross(da,db)+eps); c1 = cross(da,v1); c2 = cross(db,v1)
            u64 nw = F2FMA(nday2[q], ndx2, F2FMA(dax2[q], ndy2, neps2));
            u64 c1 = F2FMA(dax2[q], v1y, F2MUL(nday2[q], v1x));
            u64 c2 = F2SUB(F2MUL(ndy2, v1x), F2MUL(ndx2, v1y));
            u64 s1 = F2MUL(c1, F2ADD(c1, nw));      // half-hit iff sign set
            u64 s2 = F2MUL(c2, F2ADD(c2, nw));
            hbits[q] |= (s1 & s2);                  // LOP3 sign-AND, OR-accumulate
        }
    }
    #pragma unroll
    for (int off = 16; off; off >>= 1) {
        #pragma unroll
        for (int j = 0; j < M; j++)
            mind2[j] = fminf(mind2[j], __shfl_xor_sync(0xffffffffu, mind2[j], off));
        #pragma unroll
        for (int q = 0; q < 2; q++)
            hbits[q] |= __shfl_xor_sync(0xffffffffu, hbits[q], off);
    }

    if (l == 0) {
        float acc = 0.0f;
        #pragma unroll
        for (int j = 0; j < M; j++) {
            u64 hb = hbits[j >> 1];
            unsigned hw = (j & 1) ? (unsigned)(hb >> 32) : (unsigned)hb;
            float md = sqrtf(mind2[j]);
            md = (hw & 0x80000000u) ? md : -md;   // sign set => intersect => outside
            acc += fmaxf(md + THRESH_, 0.0f);
        }
        sVal[w] = acc;
    }
    __syncthreads();

    // block 0 of each (b,c) pair stores its half; second arrival combines.
    if (tid == 0) {
        float bsum = 0.0f;
        #pragma unroll
        for (int i = 0; i < WARPS; i++) bsum += sVal[i];
        g_scratch[idx * 2 + half] = bsum;
        __threadfence();
        unsigned old = atomicAdd(&g_tick[idx], 1u);
        if (old == 1u) {
            out[idx] = g_scratch[idx * 2] + g_scratch[idx * 2 + 1];
            g_tick[idx] = 0u;               // reset for next graph replay
        }
    }
}

extern "C" void kernel_launch(void* const* d_in, const int* in_sizes, int n_in,
                              void* d_out, int out_size) {
    const float* points      = (const float*)d_in[0];
    const float* road_bound  = (const float*)d_in[1];
    const float* centerlines = (const float*)d_in[2];
    float* out = (float*)d_out;
    (void)in_sizes; (void)n_in; (void)out_size;

    offroad_kernel<<<B_ * C_ * HALVES, THREADS>>>(points, road_bound, centerlines, out);
}